// round 16
// baseline (speedup 1.0000x reference)
#include <cuda_runtime.h>
#include <cuda_bf16.h>
#include <stdint.h>
#include <float.h>
#include <math.h>

#define BATCH 2
#define SEQ   2048
#define DIM   512
#define NHEAD 8
#define HDIM  64
#define NHID  128
#define NRAND 2097152
#define MROWS (BATCH*SEQ)          // 4096
#define L2M   ((size_t)SEQ*SEQ)    // 4194304

// ------------------------------- scratch ------------------------------------
__device__ float g_qn[MROWS*DIM];
__device__ float g_kn[MROWS*DIM];
__device__ float g_vn[MROWS*DIM];
__device__ float g_Q [BATCH*NHEAD*HDIM*SEQ];   // [b,h,d,s]  (transposed)
__device__ float g_K [BATCH*NHEAD*HDIM*SEQ];   // [b,h,d,s]  (transposed)
__device__ float g_V [BATCH*NHEAD*SEQ*HDIM];   // [b,h,s,d]
__device__ float g_O [MROWS*DIM];              // [b,s, h*d]
__device__ float g_hid[MROWS*NHID];
__device__ unsigned char g_m[(size_t)BATCH*L2M];     // sparse mask
__device__ unsigned char g_kp[MROWS];
__device__ unsigned char g_colm[MROWS];
__device__ int   g_win[MROWS];
__device__ float g_dm[MROWS], g_imp[MROWS], g_rv[MROWS];
__device__ float g_thr[BATCH], g_lo[BATCH], g_hi[BATCH], g_comp[BATCH], g_ratio[BATCH];
__device__ int   g_haskp[BATCH], g_cnt[BATCH], g_needed[BATCH];

// --------------------------- packed f32x2 helpers ----------------------------
__device__ __forceinline__ unsigned long long dup2(float a) {
  unsigned long long r;
  asm("mov.b64 %0, {%1, %1};" : "=l"(r) : "r"(__float_as_uint(a)));
  return r;
}
__device__ __forceinline__ void ffma2(unsigned long long& d,
                                      unsigned long long a, unsigned long long b) {
  asm("fma.rn.f32x2 %0, %1, %2, %0;" : "+l"(d) : "l"(a), "l"(b));
}
__device__ __forceinline__ void fmul2(unsigned long long& d, unsigned long long a) {
  asm("mul.rn.f32x2 %0, %0, %1;" : "+l"(d) : "l"(a));
}
__device__ __forceinline__ float2 unpack2(unsigned long long v) {
  unsigned int lo, hi;
  asm("mov.b64 {%0, %1}, %2;" : "=r"(lo), "=r"(hi) : "l"(v));
  return make_float2(__uint_as_float(lo), __uint_as_float(hi));
}

// ------------------------------ cp.async helpers -----------------------------
__device__ __forceinline__ void cpasync16(uint32_t saddr, const void* gaddr) {
  asm volatile("cp.async.cg.shared.global [%0], [%1], 16;" :: "r"(saddr), "l"(gaddr));
}
#define CP_COMMIT() asm volatile("cp.async.commit_group;" ::: "memory")
#define CP_WAIT(n)  asm volatile("cp.async.wait_group %0;" :: "n"(n) : "memory")
__device__ __forceinline__ uint32_t s2u(const void* p) {
  return (uint32_t)__cvta_generic_to_shared(p);
}

// --------------------------- threefry2x32 (JAX) -----------------------------
__host__ __device__ __forceinline__ void tf2x32(uint32_t k0, uint32_t k1,
                                                uint32_t x0, uint32_t x1,
                                                uint32_t* o0, uint32_t* o1) {
  uint32_t ks2 = k0 ^ k1 ^ 0x1BD11BDAu;
#define TFR(r) { x0 += x1; x1 = (x1 << (r)) | (x1 >> (32 - (r))); x1 ^= x0; }
  x0 += k0;  x1 += k1;
  TFR(13) TFR(15) TFR(26) TFR(6)  x0 += k1;  x1 += ks2 + 1u;
  TFR(17) TFR(29) TFR(16) TFR(24) x0 += ks2; x1 += k0 + 2u;
  TFR(13) TFR(15) TFR(26) TFR(6)  x0 += k0;  x1 += k1 + 3u;
  TFR(17) TFR(29) TFR(16) TFR(24) x0 += k1;  x1 += ks2 + 4u;
  TFR(13) TFR(15) TFR(26) TFR(6)  x0 += ks2; x1 += k0 + 5u;
#undef TFR
  *o0 = x0; *o1 = x1;
}

__device__ __forceinline__ float* devbuf(int s) {
  switch (s) {
    case 0: return g_qn;  case 1: return g_kn;  case 2: return g_vn;
    case 3: return g_Q;   case 4: return g_K;   case 5: return g_V;
    case 6: return g_hid; case 7: return g_O;
    default: return 0;
  }
}

// ------------------------------ LayerNorm -----------------------------------
__global__ void ln_kernel(const float* __restrict__ x,
                          const float* __restrict__ gam,
                          const float* __restrict__ bet, int dsel) {
  int row = blockIdx.x, tid = threadIdx.x;
  const float* xr = x + (size_t)row * DIM;
  float v0 = xr[tid], v1 = xr[tid + 256];
  __shared__ float red[256];
  red[tid] = v0 + v1; __syncthreads();
  for (int o = 128; o; o >>= 1) { if (tid < o) red[tid] += red[tid + o]; __syncthreads(); }
  float mu = red[0] * (1.0f / DIM); __syncthreads();
  float d0 = v0 - mu, d1 = v1 - mu;
  red[tid] = d0 * d0 + d1 * d1; __syncthreads();
  for (int o = 128; o; o >>= 1) { if (tid < o) red[tid] += red[tid + o]; __syncthreads(); }
  float inv = rsqrtf(red[0] * (1.0f / DIM) + 1e-5f);
  float* y = devbuf(dsel) + (size_t)row * DIM;
  y[tid]       = d0 * inv * gam[tid]       + bet[tid];
  y[tid + 256] = d1 * inv * gam[tid + 256] + bet[tid + 256];
}

// ------------------------ GEMM inner-loop core (shared) ----------------------
// 128x128 tile, TK=8, 8x8 microtile as 2x2 blocks of 4x4 at offsets {0,64}.
#define GEMM_CORE(A_, B_, lda_, ldb_, K_)                                     \
  const float* Ap = A_ + (size_t)(row0 + lr) * lda_ + lk;                     \
  const float* Bp = B_ + (size_t)(col0 + lr) * ldb_ + lk;                     \
  float4 a4 = *(const float4*)Ap;                                             \
  float4 b4 = *(const float4*)Bp;                                             \
  for (int k0 = 0; k0 < K_; k0 += 8) {                                        \
    As[lk + 0][lr] = a4.x; As[lk + 1][lr] = a4.y;                             \
    As[lk + 2][lr] = a4.z; As[lk + 3][lr] = a4.w;                             \
    Bs[lk + 0][lr] = b4.x; Bs[lk + 1][lr] = b4.y;                             \
    Bs[lk + 2][lr] = b4.z; Bs[lk + 3][lr] = b4.w;                             \
    __syncthreads();                                                          \
    if (k0 + 8 < K_) {                                                        \
      Ap += 8; Bp += 8;                                                       \
      a4 = *(const float4*)Ap;                                                \
      b4 = *(const float4*)Bp;                                                \
    }                                                                         \
    _Pragma("unroll")                                                         \
    for (int kk = 0; kk < 8; kk++) {                                          \
      const unsigned long long* brow =                                        \
          (const unsigned long long*)&Bs[kk][0];                              \
      unsigned long long b2_0 = brow[(tx << 1) + 0];                          \
      unsigned long long b2_1 = brow[(tx << 1) + 1];                          \
      unsigned long long b2_2 = brow[32 + (tx << 1) + 0];                     \
      unsigned long long b2_3 = brow[32 + (tx << 1) + 1];                     \
      float4 av0 = *(const float4*)&As[kk][ty << 2];                          \
      float4 av1 = *(const float4*)&As[kk][64 + (ty << 2)];                   \
      float ar[8] = {av0.x, av0.y, av0.z, av0.w, av1.x, av1.y, av1.z, av1.w}; \
      _Pragma("unroll")                                                       \
      for (int rr = 0; rr < 8; rr++) {                                        \
        unsigned long long a = dup2(ar[rr]);                                  \
        ffma2(acc[rr][0], a, b2_0); ffma2(acc[rr][1], a, b2_1);               \
        ffma2(acc[rr][2], a, b2_2); ffma2(acc[rr][3], a, b2_3);               \
      }                                                                       \
    }                                                                         \
    __syncthreads();                                                          \
  }

// ---------------------- fused QKV projection (grid.z=3) ----------------------
__global__ void __launch_bounds__(256, 2) qkv_kernel(
    const float* __restrict__ Wq, const float* __restrict__ Wk,
    const float* __restrict__ Wv,
    const float* __restrict__ bq, const float* __restrict__ bk,
    const float* __restrict__ bv) {
  int z = blockIdx.z;
  const float* A = (z == 0) ? g_qn : (z == 1) ? g_kn : g_vn;
  const float* B = (z == 0) ? Wq : (z == 1) ? Wk : Wv;
  const float* bias = (z == 0) ? bq : (z == 1) ? bk : bv;
  float* C = (z == 0) ? g_Q : (z == 1) ? g_K : g_V;
  int row0 = blockIdx.y * 128, col0 = blockIdx.x * 128;
  __shared__ float As[8][132];
  __shared__ float Bs[8][132];
  int tid = threadIdx.x;
  int lr = tid >> 1, lk = (tid & 1) << 2;
  int ty = tid >> 4, tx = tid & 15;
  unsigned long long acc[8][4];
#pragma unroll
  for (int i = 0; i < 8; i++)
#pragma unroll
    for (int j = 0; j < 4; j++) acc[i][j] = 0ull;

  GEMM_CORE(A, B, DIM, DIM, DIM)

#pragma unroll
  for (int rh = 0; rh < 2; rh++) {
#pragma unroll
    for (int ii = 0; ii < 4; ii++) {
      int i = row0 + rh * 64 + (ty << 2) + ii;
      int rr = rh * 4 + ii;
      int b = i >> 11, s = i & 2047;
#pragma unroll
      for (int ch = 0; ch < 2; ch++) {
        int j0 = col0 + ch * 64 + (tx << 2);
        float2 pA = unpack2(acc[rr][ch * 2 + 0]);
        float2 pB = unpack2(acc[rr][ch * 2 + 1]);
        float cv[4] = {pA.x + bias[j0], pA.y + bias[j0 + 1],
                       pB.x + bias[j0 + 2], pB.y + bias[j0 + 3]};
        if (z < 2) {  // HEADST: [b,h,d,s]
#pragma unroll
          for (int jj = 0; jj < 4; jj++) {
            int j = j0 + jj;
            int h = j >> 6, d = j & 63;
            C[(((size_t)(b * NHEAD + h)) * HDIM + d) * SEQ + s] = cv[jj];
          }
        } else {      // HEADS: [b,h,s,d]
          int h = j0 >> 6, d = j0 & 63;
          *(float4*)&C[(((size_t)(b * NHEAD + h)) * SEQ + s) * HDIM + d] =
              make_float4(cv[0], cv[1], cv[2], cv[3]);
        }
      }
    }
  }
}

// ------------------------------- GEMM (NT) ----------------------------------
// flags: 1=bias, 2=residual, 4=relu
__global__ void __launch_bounds__(256, 2) gemm_kernel(
    int asel, int lda,
    const float* __restrict__ Bext, int ldb,
    float* __restrict__ Cext, int csel, int ldc,
    const float* __restrict__ bias, const float* __restrict__ resid,
    int K, int flags) {
  const float* A = (const float*)devbuf(asel);
  const float* B = Bext;
  float*       C = Cext ? Cext : devbuf(csel);
  int row0 = blockIdx.y * 128, col0 = blockIdx.x * 128;
  __shared__ float As[8][132];
  __shared__ float Bs[8][132];
  int tid = threadIdx.x;
  int lr = tid >> 1, lk = (tid & 1) << 2;
  int ty = tid >> 4, tx = tid & 15;
  unsigned long long acc[8][4];
#pragma unroll
  for (int i = 0; i < 8; i++)
#pragma unroll
    for (int j = 0; j < 4; j++) acc[i][j] = 0ull;

  GEMM_CORE(A, B, lda, ldb, K)

#pragma unroll
  for (int rh = 0; rh < 2; rh++) {
#pragma unroll
    for (int ii = 0; ii < 4; ii++) {
      int i = row0 + rh * 64 + (ty << 2) + ii;
      int rr = rh * 4 + ii;
#pragma unroll
      for (int ch = 0; ch < 2; ch++) {
        int j0 = col0 + ch * 64 + (tx << 2);
        float2 pA = unpack2(acc[rr][ch * 2 + 0]);
        float2 pB = unpack2(acc[rr][ch * 2 + 1]);
        float cv[4] = {pA.x, pA.y, pB.x, pB.y};
        if (flags & 1) {
#pragma unroll
          for (int jj = 0; jj < 4; jj++) cv[jj] += bias[j0 + jj];
        }
        if (flags & 4) {
#pragma unroll
          for (int jj = 0; jj < 4; jj++) cv[jj] = fmaxf(cv[jj], 0.0f);
        }
        if (flags & 2) {
          const float* rp = resid + (size_t)i * ldc + j0;
#pragma unroll
          for (int jj = 0; jj < 4; jj++) cv[jj] += rp[jj];
        }
        *(float4*)&C[(size_t)i * ldc + j0] =
            make_float4(cv[0], cv[1], cv[2], cv[3]);
      }
    }
  }
}

// ------------------- hidden-MLP GEMM: 64x64 tiles, K=512 ---------------------
// g_hid[4096,128] = relu(g_qn . Ww1^T + bw1); grid (2, 64) = 128 blocks.
__global__ void __launch_bounds__(256) hid_kernel(
    const float* __restrict__ Ww1, const float* __restrict__ bw1) {
  int row0 = blockIdx.y * 64, col0 = blockIdx.x * 64;
  __shared__ float As[16][68];
  __shared__ float Bs[16][68];
  int tid = threadIdx.x;
  int lr = tid >> 2, lk = (tid & 3) << 2;
  int ty = tid >> 4, tx = tid & 15;
  unsigned long long acc[4][2];
#pragma unroll
  for (int i = 0; i < 4; i++) { acc[i][0] = 0ull; acc[i][1] = 0ull; }
  const float* Ap = g_qn + (size_t)(row0 + lr) * DIM + lk;
  const float* Bp = Ww1 + (size_t)(col0 + lr) * DIM + lk;
  float4 a4 = *(const float4*)Ap;
  float4 b4 = *(const float4*)Bp;
  for (int k0 = 0; k0 < DIM; k0 += 16) {
    As[lk + 0][lr] = a4.x; As[lk + 1][lr] = a4.y;
    As[lk + 2][lr] = a4.z; As[lk + 3][lr] = a4.w;
    Bs[lk + 0][lr] = b4.x; Bs[lk + 1][lr] = b4.y;
    Bs[lk + 2][lr] = b4.z; Bs[lk + 3][lr] = b4.w;
    __syncthreads();
    if (k0 + 16 < DIM) {
      Ap += 16; Bp += 16;
      a4 = *(const float4*)Ap;
      b4 = *(const float4*)Bp;
    }
#pragma unroll
    for (int kk = 0; kk < 16; kk++) {
      const unsigned long long* brow = (const unsigned long long*)&Bs[kk][0];
      unsigned long long b0 = brow[(tx << 1) + 0];
      unsigned long long b1 = brow[(tx << 1) + 1];
      float4 av = *(const float4*)&As[kk][ty << 2];
      unsigned long long a;
      a = dup2(av.x); ffma2(acc[0][0], a, b0); ffma2(acc[0][1], a, b1);
      a = dup2(av.y); ffma2(acc[1][0], a, b0); ffma2(acc[1][1], a, b1);
      a = dup2(av.z); ffma2(acc[2][0], a, b0); ffma2(acc[2][1], a, b1);
      a = dup2(av.w); ffma2(acc[3][0], a, b0); ffma2(acc[3][1], a, b1);
    }
    __syncthreads();
  }
#pragma unroll
  for (int ii = 0; ii < 4; ii++) {
    int i = row0 + (ty << 2) + ii;
    int j0 = col0 + (tx << 2);
    float2 p0 = unpack2(acc[ii][0]);
    float2 p1 = unpack2(acc[ii][1]);
    float4 o;
    o.x = fmaxf(p0.x + bw1[j0 + 0], 0.0f);
    o.y = fmaxf(p0.y + bw1[j0 + 1], 0.0f);
    o.z = fmaxf(p1.x + bw1[j0 + 2], 0.0f);
    o.w = fmaxf(p1.y + bw1[j0 + 3], 0.0f);
    *(float4*)&g_hid[(size_t)i * NHID + j0] = o;
  }
}

// -------------------- fused flash attention (mask-aware) ---------------------
// grid (SEQ/64, B*H), 256 threads. Q,K in [b,h,d,s]; V in [b,h,s,d].
// Register-resident online softmax (per-thread m/l for its 4 rows).
#define NT 32           // SEQ/64 tiles
__global__ void __launch_bounds__(256, 2) flash_kernel() {
  extern __shared__ float sm[];
  float* Qs = sm;                        // [64][68] (d-major)
  float* Ks = Qs + 64 * 68;              // [2][64][68] (d-major)
  float* Vs = Ks + 2 * 64 * 68;          // [64][68] (s-major)
  float* Ps = Vs + 64 * 68;              // [64][68] row-major [q][k]
  unsigned char* Ms = (unsigned char*)(Ps + 64 * 68);   // [2][64][64]

  int z = blockIdx.y;
  int q0 = blockIdx.x * 64;
  const float* Qg = g_Q + (size_t)z * HDIM * SEQ;
  const float* Kg = g_K + (size_t)z * HDIM * SEQ;
  const float* Vg = g_V + (size_t)z * SEQ * HDIM;
  const unsigned char* Mg = g_m + (size_t)(z >> 3) * L2M;

  int tid = threadIdx.x;
  int lr = tid >> 2, lc = (tid & 3) << 4;     // loader: row 0..63, 16-col chunk
  int ty = tid >> 4, tx = tid & 15;           // compute microtile

  // Q tile (persistent): Qs[d][i] = Qg[d][q0+i]
  {
    const float* src = Qg + (size_t)lr * SEQ + q0 + lc;
    float4* dst = (float4*)&Qs[lr * 68 + lc];
#pragma unroll
    for (int u = 0; u < 4; u++) dst[u] = *(const float4*)(src + u * 4);
  }

  // prologue: prefetch K(0), M(0) into buffer 0
  {
    uint32_t kd = s2u(&Ks[lr * 68 + lc]);
    const float* ksrc = Kg + (size_t)lr * SEQ + lc;
#pragma unroll
    for (int u = 0; u < 4; u++) cpasync16(kd + u * 16, ksrc + u * 4);
    cpasync16(s2u(&Ms[lr * 64 + lc]), Mg + (size_t)(q0 + lr) * SEQ + lc);
  }
  CP_COMMIT();

  unsigned long long acc[4][2];
#pragma unroll
  for (int i = 0; i < 4; i++) { acc[i][0] = 0ull; acc[i][1] = 0ull; }
  float m_run[4], l_run[4];
#pragma unroll
  for (int i = 0; i < 4; i++) { m_run[i] = -INFINITY; l_run[i] = 0.0f; }

  for (int t = 0; t < NT; t++) {
    int j0 = t * 64;
    int buf = t & 1;
    float* Kb = Ks + buf * 64 * 68;
    unsigned char* Mb = Ms + buf * 64 * 64;
    __syncthreads();   // prev GEMM2 done (Vs/Ps free), Ks/Ms[buf^1] free

    // group A: V(t)
    {
      uint32_t vd = s2u(&Vs[lr * 68 + lc]);
      const float* vsrc = Vg + (size_t)(j0 + lr) * HDIM + lc;
#pragma unroll
      for (int u = 0; u < 4; u++) cpasync16(vd + u * 16, vsrc + u * 4);
    }
    CP_COMMIT();
    // group B: K(t+1), M(t+1) into the other buffer
    if (t + 1 < NT) {
      float* Kn = Ks + (buf ^ 1) * 64 * 68;
      unsigned char* Mn = Ms + (buf ^ 1) * 64 * 64;
      uint32_t kd = s2u(&Kn[lr * 68 + lc]);
      const float* ksrc = Kg + (size_t)lr * SEQ + j0 + 64 + lc;
#pragma unroll
      for (int u = 0; u < 4; u++) cpasync16(kd + u * 16, ksrc + u * 4);
      cpasync16(s2u(&Mn[lr * 64 + lc]), Mg + (size_t)(q0 + lr) * SEQ + j0 + 64 + lc);
    }
    CP_COMMIT();

    CP_WAIT(2);        // K(t), M(t) have landed
    __syncthreads();

    // ---- GEMM1: S = Q^T K (64x64x64), B pairs via LDS.64 ----
    unsigned long long s2r[4][2];
#pragma unroll
    for (int i = 0; i < 4; i++) { s2r[i][0] = 0ull; s2r[i][1] = 0ull; }
#pragma unroll 16
    for (int d = 0; d < 64; d++) {
      const unsigned long long* brow = (const unsigned long long*)&Kb[d * 68];
      unsigned long long b0 = brow[(tx << 1) + 0];
      unsigned long long b1 = brow[(tx << 1) + 1];
      float4 av = *(const float4*)&Qs[d * 68 + (ty << 2)];
      unsigned long long a;
      a = dup2(av.x); ffma2(s2r[0][0], a, b0); ffma2(s2r[0][1], a, b1);
      a = dup2(av.y); ffma2(s2r[1][0], a, b0); ffma2(s2r[1][1], a, b1);
      a = dup2(av.z); ffma2(s2r[2][0], a, b0); ffma2(s2r[2][1], a, b1);
      a = dup2(av.w); ffma2(s2r[3][0], a, b0); ffma2(s2r[3][1], a, b1);
    }

    // ---- register-resident mask + online softmax ----
    // Row gi = (ty<<2)+ii is shared by the 16 lanes with the same ty
    // (lane = (ty&1)*16 + tx), so xor 1,2,4,8 reduces within the row group.
#pragma unroll
    for (int ii = 0; ii < 4; ii++) {
      int gi = (ty << 2) + ii;
      float2 p0 = unpack2(s2r[ii][0]);
      float2 p1 = unpack2(s2r[ii][1]);
      uchar4 mm = *(const uchar4*)&Mb[gi * 64 + (tx << 2)];
      float v0 = mm.x ? -FLT_MAX : p0.x * 0.125f;
      float v1 = mm.y ? -FLT_MAX : p0.y * 0.125f;
      float v2 = mm.z ? -FLT_MAX : p1.x * 0.125f;
      float v3 = mm.w ? -FLT_MAX : p1.y * 0.125f;
      float rm = fmaxf(fmaxf(v0, v1), fmaxf(v2, v3));
      rm = fmaxf(rm, __shfl_xor_sync(0xffffffffu, rm, 1));
      rm = fmaxf(rm, __shfl_xor_sync(0xffffffffu, rm, 2));
      rm = fmaxf(rm, __shfl_xor_sync(0xffffffffu, rm, 4));
      rm = fmaxf(rm, __shfl_xor_sync(0xffffffffu, rm, 8));
      float mn = fmaxf(m_run[ii], rm);
      float al = __expf(m_run[ii] - mn);
      v0 = __expf(v0 - mn); v1 = __expf(v1 - mn);
      v2 = __expf(v2 - mn); v3 = __expf(v3 - mn);
      float ps = (v0 + v1) + (v2 + v3);
      ps += __shfl_xor_sync(0xffffffffu, ps, 1);
      ps += __shfl_xor_sync(0xffffffffu, ps, 2);
      ps += __shfl_xor_sync(0xffffffffu, ps, 4);
      ps += __shfl_xor_sync(0xffffffffu, ps, 8);
      l_run[ii] = l_run[ii] * al + ps;
      m_run[ii] = mn;
      // rescale accumulator row by al (in registers, no smem)
      unsigned long long a2 = dup2(al);
      fmul2(acc[ii][0], a2);
      fmul2(acc[ii][1], a2);
      *(float4*)&Ps[gi * 68 + (tx << 2)] = make_float4(v0, v1, v2, v3);
    }
    CP_WAIT(1);        // V(t) landed (group B may still be in flight)
    __syncthreads();   // Ps visible to all, Vs ready

    // ---- GEMM2: O += P V (vector P reads, LDS.64 V pairs) ----
#pragma unroll 4
    for (int k4 = 0; k4 < 64; k4 += 4) {
      float4 pr0 = *(const float4*)&Ps[((ty << 2) + 0) * 68 + k4];
      float4 pr1 = *(const float4*)&Ps[((ty << 2) + 1) * 68 + k4];
      float4 pr2 = *(const float4*)&Ps[((ty << 2) + 2) * 68 + k4];
      float4 pr3 = *(const float4*)&Ps[((ty << 2) + 3) * 68 + k4];
      float p0a[4] = {pr0.x, pr0.y, pr0.z, pr0.w};
      float p1a[4] = {pr1.x, pr1.y, pr1.z, pr1.w};
      float p2a[4] = {pr2.x, pr2.y, pr2.z, pr2.w};
      float p3a[4] = {pr3.x, pr3.y, pr3.z, pr3.w};
#pragma unroll
      for (int u = 0; u < 4; u++) {
        const unsigned long long* vrow =
            (const unsigned long long*)&Vs[(k4 + u) * 68];
        unsigned long long b0 = vrow[(tx << 1) + 0];
        unsigned long long b1 = vrow[(tx << 1) + 1];
        unsigned long long a;
        a = dup2(p0a[u]); ffma2(acc[0][0], a, b0); ffma2(acc[0][1], a, b1);
        a = dup2(p1a[u]); ffma2(acc[1][0], a, b0); ffma2(acc[1][1], a, b1);
        a = dup2(p2a[u]); ffma2(acc[2][0], a, b0); ffma2(acc[2][1], a, b1);
        a = dup2(p3a[u]); ffma2(acc[3][0], a, b0); ffma2(acc[3][1], a, b1);
      }
    }
  }

  int b = z >> 3, h = z & 7;
#pragma unroll
  for (int ii = 0; ii < 4; ii++) {
    float inv = 1.0f / l_run[ii];
    float2 p0 = unpack2(acc[ii][0]);
    float2 p1 = unpack2(acc[ii][1]);
    float4 o = make_float4(p0.x * inv, p0.y * inv, p1.x * inv, p1.y * inv);
    *(float4*)&g_O[((size_t)(b * SEQ + q0 + (ty << 2) + ii)) * DIM
                   + h * HDIM + (tx << 2)] = o;
  }
}

// ---------------------- window MLP second layer + win -----------------------
__global__ void win_kernel(const float* __restrict__ Ww2,
                           const float* __restrict__ bw2) {
  int row = blockIdx.x, tid = threadIdx.x;  // 128 threads
  __shared__ float red[128];
  red[tid] = g_hid[(size_t)row * NHID + tid] * Ww2[tid];
  __syncthreads();
  for (int o = 64; o; o >>= 1) { if (tid < o) red[tid] += red[tid + o]; __syncthreads(); }
  if (tid == 0) {
    float x = red[0] + bw2[0];
    float adj = 0.5f + 1.0f / (1.0f + expf(-x));
    int w = (int)rintf(64.0f * adj);
    w = w < 1 ? 1 : (w > 128 ? 128 : w);
    g_win[row] = w;
  }
}

// ------------------------- per-row features (dm/imp/var) --------------------
__global__ void rowfeat_kernel() {
  int row = blockIdx.x;               // b*2048 + t
  int t = row & 2047;
  int tid = threadIdx.x;              // 128
  const float* q0 = g_qn + (size_t)row * DIM;
  float sdm = 0, sab = 0, sq = 0, sq2 = 0;
  for (int d = tid; d < DIM; d += 128) {
    float q = q0[d];
    sq += q; sq2 += q * q;
    if (t + 1 < SEQ) { float a = fabsf(q0[DIM + d] - q);      sdm += 0.4f * a; sab += a; }
    if (t + 2 < SEQ) { float a = fabsf(q0[2*DIM + d] - q) * 0.5f;         sdm += 0.3f * a; }
    if (t + 3 < SEQ) { float a = fabsf(q0[3*DIM + d] - q) * (1.0f/3.0f);  sdm += 0.2f * a; }
    if (t + 5 < SEQ) { float a = fabsf(q0[5*DIM + d] - q) * 0.2f;         sdm += 0.1f * a; }
  }
  __shared__ float red[128];
  red[tid] = sdm; __syncthreads();
  for (int o = 64; o; o >>= 1) { if (tid < o) red[tid] += red[tid + o]; __syncthreads(); }
  float Sdm = red[0]; __syncthreads();
  red[tid] = sab; __syncthreads();
  for (int o = 64; o; o >>= 1) { if (tid < o) red[tid] += red[tid + o]; __syncthreads(); }
  float Sab = red[0]; __syncthreads();
  red[tid] = sq; __syncthreads();
  for (int o = 64; o; o >>= 1) { if (tid < o) red[tid] += red[tid + o]; __syncthreads(); }
  float Sq = red[0]; __syncthreads();
  red[tid] = sq2; __syncthreads();
  for (int o = 64; o; o >>= 1) { if (tid < o) red[tid] += red[tid + o]; __syncthreads(); }
  float Sq2 = red[0];
  if (tid == 0) {
    g_dm[row] = Sdm * (1.0f / DIM);
    float ch  = Sab * (1.0f / DIM);
    float mag = sqrtf(Sq2);
    g_imp[row] = 0.5f * mag + 0.5f * ch;
    g_rv[row]  = (Sq2 - Sq * Sq * (1.0f / DIM)) * (1.0f / (DIM - 1));
  }
}

// ----------------------------- per-batch stats ------------------------------
__global__ void batchstats_kernel() {
  int b = blockIdx.x, tid = threadIdx.x;  // 512 threads
  __shared__ float red[512];
  float s = 0, sv = 0, mn = FLT_MAX, mx = -FLT_MAX;
  for (int t = tid; t < SEQ; t += 512) {
    s += g_dm[b * SEQ + t];
    sv += g_rv[b * SEQ + t];
    float im = g_imp[b * SEQ + t];
    mn = fminf(mn, im); mx = fmaxf(mx, im);
  }
  red[tid] = s; __syncthreads();
  for (int o = 256; o; o >>= 1) { if (tid < o) red[tid] += red[tid + o]; __syncthreads(); }
  float mean = red[0] * (1.0f / SEQ); __syncthreads();
  float ss = 0;
  for (int t = tid; t < SEQ; t += 512) { float d = g_dm[b * SEQ + t] - mean; ss += d * d; }
  red[tid] = ss; __syncthreads();
  for (int o = 256; o; o >>= 1) { if (tid < o) red[tid] += red[tid + o]; __syncthreads(); }
  float stdv = sqrtf(red[0] * (1.0f / (SEQ - 1))); __syncthreads();
  red[tid] = sv; __syncthreads();
  for (int o = 256; o; o >>= 1) { if (tid < o) red[tid] += red[tid + o]; __syncthreads(); }
  float comp = red[0] * (1.0f / SEQ); __syncthreads();
  red[tid] = mn; __syncthreads();
  for (int o = 256; o; o >>= 1) { if (tid < o) red[tid] = fminf(red[tid], red[tid + o]); __syncthreads(); }
  float lo = red[0]; __syncthreads();
  red[tid] = mx; __syncthreads();
  for (int o = 256; o; o >>= 1) { if (tid < o) red[tid] = fmaxf(red[tid], red[tid + o]); __syncthreads(); }
  if (tid == 0) {
    g_thr[b] = mean + 0.5f * stdv;
    g_comp[b] = comp; g_lo[b] = lo; g_hi[b] = red[0];
  }
}

// ------------------- ratio + zero transient accumulators --------------------
__global__ void ratio_kernel() {
  int tid = threadIdx.x;
  if (tid < BATCH) {
    float c0 = g_comp[0], c1 = g_comp[1];
    float cmin = fminf(c0, c1), cmax = fmaxf(c0, c1);
    float nc = (g_comp[tid] - cmin) / (cmax - cmin + 1e-6f);
    float r = 0.3f * (0.5f + nc);
    g_ratio[tid] = fminf(fmaxf(r, 0.1f), 0.5f);
    g_haskp[tid] = 0; g_cnt[tid] = 0;
  }
  for (int i = tid; i < MROWS; i += 256) g_colm[i] = 0;
}

// ------------------------------- keypoints ----------------------------------
__global__ void kp_kernel() {
  int idx = blockIdx.x * 256 + threadIdx.x;
  if (idx >= MROWS) return;
  int b = idx >> 11, t = idx & 2047;
  float d = g_dm[idx], thr = g_thr[b];
  float l = (t > 0)       ? g_dm[idx - 1] : -1.0f;
  float r = (t < SEQ - 1) ? g_dm[idx + 1] : -1.0f;
  bool kp = (d > thr) && (d > l) && (d > r);
  if (t == 0 || t == SEQ - 1) kp = kp || (d > thr);
  g_kp[idx] = kp ? 1 : 0;
  if (kp) atomicOr(&g_haskp[b], 1);
}

// ----------------------- gumbel top-4 per segment ---------------------------
__global__ void gumbel_kernel(uint32_t kg0, uint32_t kg1) {
  int r = blockIdx.x;          // 0..7 = b*4 + layer
  int b = r >> 2, layer = r & 3;
  int j = threadIdx.x;         // 512
  __shared__ float red[512];
  __shared__ int   ridx[512];
  float lo = g_lo[b], hi = g_hi[b];
  float impn = (g_imp[b * SEQ + layer * 512 + j] - lo) / (hi - lo + 1e-6f);
  red[j] = impn; __syncthreads();
  for (int o = 256; o; o >>= 1) { if (j < o) red[j] += red[j + o]; __syncthreads(); }
  float rsum = red[0]; __syncthreads();
  float prob = impn / (rsum + 1e-6f);
  uint32_t x0, x1;
  tf2x32(kg0, kg1, 0u, (uint32_t)(r * 512 + j), &x0, &x1);
  uint32_t bits = x0 ^ x1;
  float u = __uint_as_float((bits >> 9) | 0x3f800000u) - 1.0f;
  const float TINY = 1.17549435e-38f;
  u = u * (1.0f - TINY) + TINY;
  u = fmaxf(TINY, u);
  float score = logf(prob + 1e-20f) - logf(-logf(u));
  float myv = score;
  for (int pick = 0; pick < 4; pick++) {
    red[j] = myv; ridx[j] = j; __syncthreads();
    for (int o = 256; o; o >>= 1) {
      if (j < o) {
        float v2 = red[j + o]; int i2 = ridx[j + o];
        if (v2 > red[j] || (v2 == red[j] && i2 < ridx[j])) { red[j] = v2; ridx[j] = i2; }
      }
      __syncthreads();
    }
    int w = ridx[0];
    if (j == w) myv = -INFINITY;
    if (j == 0) g_colm[b * SEQ + layer * 512 + w] = 1;
    __syncthreads();
  }
}

// -------------------------- mask build + popcount ---------------------------
__device__ __forceinline__ int isfb(int k) {
  return (k == 0) | (k == 511) | (k == 1023) | (k == 1535) | (k == 2047);
}
__global__ void maskbuild_kernel() {
  int row = blockIdx.x;
  int b = row >> 11, q = row & 2047;
  int w = g_win[row];
  int haskp = g_haskp[b];
  int kpq = g_kp[row];
  int fbq = isfb(q);
  unsigned char* mrow = g_m + (size_t)b * L2M + (size_t)q * SEQ;
  const unsigned char* kprow = g_kp + b * SEQ;
  const unsigned char* crow = g_colm + b * SEQ;
  int lo = q - w, hi = q + w;
  int cnt = 0;
  for (int k = threadIdx.x; k < SEQ; k += 256) {
    int v = (k >= lo) & (k <= hi);
    if (haskp) v |= kpq | kprow[k];
    else       v |= fbq | isfb(k);
    v |= crow[k];
    v = v ? 1 : 0;
    mrow[k] = (unsigned char)v;
    cnt += v;
  }
  __shared__ int red[256];
  red[threadIdx.x] = cnt; __syncthreads();
  for (int o = 128; o; o >>= 1) { if (threadIdx.x < o) red[threadIdx.x] += red[threadIdx.x + o]; __syncthreads(); }
  if (threadIdx.x == 0) atomicAdd(&g_cnt[b], red[0]);
}

__global__ void needed_kernel() {
  int b = threadIdx.x;
  if (b >= BATCH) return;
  float dens = (float)g_cnt[b] * (1.0f / 4194304.0f);
  float nf = ceilf((g_ratio[b] - dens) * 4194304.0f);
  int n = (int)nf;
  g_needed[b] = n < 0 ? 0 : n;
}

__global__ void randfill_kernel(uint32_t q0, uint32_t q1, uint32_t k0, uint32_t k1) {
  int j = blockIdx.x * 256 + threadIdx.x;
  int b = blockIdx.y;
  if (j >= g_needed[b]) return;
  uint32_t i = (uint32_t)(b * NRAND + j);
  uint32_t a, c;
  tf2x32(q0, q1, 0u, i, &a, &c);
  uint32_t qr = (a ^ c) & 2047u;
  tf2x32(k0, k1, 0u, i, &a, &c);
  uint32_t kr = (a ^ c) & 2047u;
  g_m[(size_t)b * L2M + (size_t)qr * SEQ + kr] = 1;
}

// -------------------------------- launch ------------------------------------
extern "C" void kernel_launch(void* const* d_in, const int* in_sizes, int n_in,
                              void* d_out, int out_size) {
  (void)in_sizes; (void)n_in; (void)out_size;
  const float* queries = (const float*)d_in[0];
  const float* keys    = (const float*)d_in[1];
  const float* values  = (const float*)d_in[2];
  const float* lnqg = (const float*)d_in[3];  const float* lnqb = (const float*)d_in[4];
  const float* lnkg = (const float*)d_in[5];  const float* lnkb = (const float*)d_in[6];
  const float* lnvg = (const float*)d_in[7];  const float* lnvb = (const float*)d_in[8];
  const float* Wq = (const float*)d_in[9];   const float* bq = (const float*)d_in[10];
  const float* Wk = (const float*)d_in[11];  const float* bk = (const float*)d_in[12];
  const float* Wv = (const float*)d_in[13];  const float* bv = (const float*)d_in[14];
  const float* Wo = (const float*)d_in[15];  const float* bo = (const float*)d_in[16];
  const float* Ww1 = (const float*)d_in[17]; const float* bw1 = (const float*)d_in[18];
  const float* Ww2 = (const float*)d_in[19]; const float* bw2 = (const float*)d_in[20];
  float* out = (float*)d_out;

  // lazily-created side stream + fork/join events (host objects only)
  static cudaStream_t s2 = 0;
  static cudaEvent_t evFork = 0, evJoin = 0;
  if (!s2) {
    cudaStreamCreateWithFlags(&s2, cudaStreamNonBlocking);
    cudaEventCreateWithFlags(&evFork, cudaEventDisableTiming);
    cudaEventCreateWithFlags(&evJoin, cudaEventDisableTiming);
  }

  // JAX PRNG derived keys (host-side, deterministic)
  uint32_t kg0, kg1, kq0, kq1, kk0, kk1, kql0, kql1, kkl0, kkl1;
  tf2x32(0u, 42u, 0u, 0u, &kg0, &kg1);     // fold_in(key(42), 0) -> gumbel
  tf2x32(0u, 42u, 0u, 1u, &kq0, &kq1);     // fold_in(key(42), 1) -> qr base
  tf2x32(0u, 42u, 0u, 2u, &kk0, &kk1);     // fold_in(key(42), 2) -> kr base
  tf2x32(kq0, kq1, 0u, 1u, &kql0, &kql1);  // split child 1 (lower bits)
  tf2x32(kk0, kk1, 0u, 1u, &kkl0, &kkl1);

  // dynamic smem for the flash kernel: Q + 2K + V + P (floats) + 2M
  const int FLASH_SMEM = 5 * 64 * 68 * 4 + 2 * 64 * 64;
  cudaFuncSetAttribute(flash_kernel, cudaFuncAttributeMaxDynamicSharedMemorySize,
                       FLASH_SMEM);

  // LN(q) first — everything the mask pipeline needs
  ln_kernel<<<MROWS, 256>>>(queries, lnqg, lnqb, 0);

  // fork: mask pipeline on s2, LN(k)/LN(v)+QKV on main
  cudaEventRecord(evFork, 0);
  cudaStreamWaitEvent(s2, evFork, 0);

  // --- s2: window MLP + mask statistics pipeline (depends only on g_qn) ---
  dim3 ghid(2, 64, 1);     // 64x64 tiles over [4096, 128]
  hid_kernel<<<ghid, 256, 0, s2>>>(Ww1, bw1);
  win_kernel<<<MROWS, 128, 0, s2>>>(Ww2, bw2);
  rowfeat_kernel<<<MROWS, 128, 0, s2>>>();
  batchstats_kernel<<<BATCH, 512, 0, s2>>>();
  ratio_kernel<<<1, 256, 0, s2>>>();
  kp_kernel<<<MROWS / 256, 256, 0, s2>>>();
  gumbel_kernel<<<BATCH * 4, 512, 0, s2>>>(kg0, kg1);
  maskbuild_kernel<<<MROWS, 256, 0, s2>>>();
  needed_kernel<<<1, 32, 0, s2>>>();
  randfill_kernel<<<dim3(NRAND / 256, BATCH, 1), 256, 0, s2>>>(kql0, kql1, kkl0, kkl1);
  cudaEventRecord(evJoin, s2);

  // --- main: LN(k), LN(v), fused QKV projections ---
  ln_kernel<<<MROWS, 256>>>(keys,   lnkg, lnkb, 1);
  ln_kernel<<<MROWS, 256>>>(values, lnvg, lnvb, 2);
  dim3 gqkv(4, 32, 3);
  qkv_kernel<<<gqkv, 256>>>(Wq, Wk, Wv, bq, bk, bv);

  // join, then fused attention
  cudaStreamWaitEvent(0, evJoin, 0);
  dim3 gf(SEQ / 64, BATCH * NHEAD, 1);
  flash_kernel<<<gf, 256, FLASH_SMEM>>>();

  // output projection + bias + residual
  dim3 gbig(4, 32, 1);
  gemm_kernel<<<gbig, 256>>>(7, DIM, Wo, DIM, out, -1, DIM, bo, queries, DIM, 1 | 2);
}

// round 17
// speedup vs baseline: 1.0229x; 1.0229x over previous
#include <cuda_runtime.h>
#include <cuda_bf16.h>
#include <stdint.h>
#include <float.h>
#include <math.h>

#define BATCH 2
#define SEQ   2048
#define DIM   512
#define NHEAD 8
#define HDIM  64
#define NHID  128
#define NRAND 2097152
#define MROWS (BATCH*SEQ)          // 4096
#define L2M   ((size_t)SEQ*SEQ)    // 4194304

// ------------------------------- scratch ------------------------------------
__device__ float g_qn[MROWS*DIM];
__device__ float g_kn[MROWS*DIM];
__device__ float g_vn[MROWS*DIM];
__device__ float g_Q [BATCH*NHEAD*HDIM*SEQ];   // [b,h,d,s]  (transposed)
__device__ float g_K [BATCH*NHEAD*HDIM*SEQ];   // [b,h,d,s]  (transposed)
__device__ float g_V [BATCH*NHEAD*SEQ*HDIM];   // [b,h,s,d]
__device__ float g_O [MROWS*DIM];              // [b,s, h*d]
__device__ float g_hid[MROWS*NHID];
__device__ unsigned char g_m[(size_t)BATCH*L2M];     // sparse mask
__device__ unsigned char g_kp[MROWS];
__device__ unsigned char g_colm[MROWS];
__device__ int   g_win[MROWS];
__device__ float g_dm[MROWS], g_imp[MROWS], g_rv[MROWS];
__device__ float g_thr[BATCH], g_lo[BATCH], g_hi[BATCH], g_comp[BATCH], g_ratio[BATCH];
__device__ int   g_haskp[BATCH], g_cnt[BATCH];

// --------------------------- packed f32x2 helpers ----------------------------
__device__ __forceinline__ unsigned long long dup2(float a) {
  unsigned long long r;
  asm("mov.b64 %0, {%1, %1};" : "=l"(r) : "r"(__float_as_uint(a)));
  return r;
}
__device__ __forceinline__ unsigned long long pack2(float x, float y) {
  unsigned long long r;
  asm("mov.b64 %0, {%1, %2};" : "=l"(r) : "r"(__float_as_uint(x)), "r"(__float_as_uint(y)));
  return r;
}
__device__ __forceinline__ void ffma2(unsigned long long& d,
                                      unsigned long long a, unsigned long long b) {
  asm("fma.rn.f32x2 %0, %1, %2, %0;" : "+l"(d) : "l"(a), "l"(b));
}
__device__ __forceinline__ void fmul2(unsigned long long& d, unsigned long long a) {
  asm("mul.rn.f32x2 %0, %0, %1;" : "+l"(d) : "l"(a));
}
__device__ __forceinline__ float2 unpack2(unsigned long long v) {
  unsigned int lo, hi;
  asm("mov.b64 {%0, %1}, %2;" : "=r"(lo), "=r"(hi) : "l"(v));
  return make_float2(__uint_as_float(lo), __uint_as_float(hi));
}

// ------------------------------ cp.async helpers -----------------------------
__device__ __forceinline__ void cpasync16(uint32_t saddr, const void* gaddr) {
  asm volatile("cp.async.cg.shared.global [%0], [%1], 16;" :: "r"(saddr), "l"(gaddr));
}
#define CP_COMMIT() asm volatile("cp.async.commit_group;" ::: "memory")
#define CP_WAIT(n)  asm volatile("cp.async.wait_group %0;" :: "n"(n) : "memory")
__device__ __forceinline__ uint32_t s2u(const void* p) {
  return (uint32_t)__cvta_generic_to_shared(p);
}

// --------------------------- threefry2x32 (JAX) -----------------------------
__host__ __device__ __forceinline__ void tf2x32(uint32_t k0, uint32_t k1,
                                                uint32_t x0, uint32_t x1,
                                                uint32_t* o0, uint32_t* o1) {
  uint32_t ks2 = k0 ^ k1 ^ 0x1BD11BDAu;
#define TFR(r) { x0 += x1; x1 = (x1 << (r)) | (x1 >> (32 - (r))); x1 ^= x0; }
  x0 += k0;  x1 += k1;
  TFR(13) TFR(15) TFR(26) TFR(6)  x0 += k1;  x1 += ks2 + 1u;
  TFR(17) TFR(29) TFR(16) TFR(24) x0 += ks2; x1 += k0 + 2u;
  TFR(13) TFR(15) TFR(26) TFR(6)  x0 += k0;  x1 += k1 + 3u;
  TFR(17) TFR(29) TFR(16) TFR(24) x0 += k1;  x1 += ks2 + 4u;
  TFR(13) TFR(15) TFR(26) TFR(6)  x0 += ks2; x1 += k0 + 5u;
#undef TFR
  *o0 = x0; *o1 = x1;
}

__device__ __forceinline__ float* devbuf(int s) {
  switch (s) {
    case 0: return g_qn;  case 1: return g_kn;  case 2: return g_vn;
    case 3: return g_Q;   case 4: return g_K;   case 5: return g_V;
    case 6: return g_hid; case 7: return g_O;
    default: return 0;
  }
}

// ----------------------- fused 3-way LayerNorm (z=3) -------------------------
__global__ void ln3_kernel(const float* __restrict__ xq,
                           const float* __restrict__ xk,
                           const float* __restrict__ xv,
                           const float* __restrict__ gq, const float* __restrict__ bq,
                           const float* __restrict__ gk, const float* __restrict__ bk,
                           const float* __restrict__ gv, const float* __restrict__ bv) {
  int z = blockIdx.y;
  const float* x  = (z == 0) ? xq : (z == 1) ? xk : xv;
  const float* gam = (z == 0) ? gq : (z == 1) ? gk : gv;
  const float* bet = (z == 0) ? bq : (z == 1) ? bk : bv;
  float* y = devbuf(z);
  int row = blockIdx.x, tid = threadIdx.x;
  const float* xr = x + (size_t)row * DIM;
  float v0 = xr[tid], v1 = xr[tid + 256];
  __shared__ float red[256];
  red[tid] = v0 + v1; __syncthreads();
  for (int o = 128; o; o >>= 1) { if (tid < o) red[tid] += red[tid + o]; __syncthreads(); }
  float mu = red[0] * (1.0f / DIM); __syncthreads();
  float d0 = v0 - mu, d1 = v1 - mu;
  red[tid] = d0 * d0 + d1 * d1; __syncthreads();
  for (int o = 128; o; o >>= 1) { if (tid < o) red[tid] += red[tid + o]; __syncthreads(); }
  float inv = rsqrtf(red[0] * (1.0f / DIM) + 1e-5f);
  float* yr = y + (size_t)row * DIM;
  yr[tid]       = d0 * inv * gam[tid]       + bet[tid];
  yr[tid + 256] = d1 * inv * gam[tid + 256] + bet[tid + 256];
}

// ------------------------ GEMM inner-loop core (shared) ----------------------
// 128x128 tile, TK=8, 8x8 microtile as 2x2 blocks of 4x4 at offsets {0,64}.
#define GEMM_CORE(A_, B_, lda_, ldb_, K_)                                     \
  const float* Ap = A_ + (size_t)(row0 + lr) * lda_ + lk;                     \
  const float* Bp = B_ + (size_t)(col0 + lr) * ldb_ + lk;                     \
  float4 a4 = *(const float4*)Ap;                                             \
  float4 b4 = *(const float4*)Bp;                                             \
  for (int k0 = 0; k0 < K_; k0 += 8) {                                        \
    As[lk + 0][lr] = a4.x; As[lk + 1][lr] = a4.y;                             \
    As[lk + 2][lr] = a4.z; As[lk + 3][lr] = a4.w;                             \
    Bs[lk + 0][lr] = b4.x; Bs[lk + 1][lr] = b4.y;                             \
    Bs[lk + 2][lr] = b4.z; Bs[lk + 3][lr] = b4.w;                             \
    __syncthreads();                                                          \
    if (k0 + 8 < K_) {                                                        \
      Ap += 8; Bp += 8;                                                       \
      a4 = *(const float4*)Ap;                                                \
      b4 = *(const float4*)Bp;                                                \
    }                                                                         \
    _Pragma("unroll")                                                         \
    for (int kk = 0; kk < 8; kk++) {                                          \
      const unsigned long long* brow =                                        \
          (const unsigned long long*)&Bs[kk][0];                              \
      unsigned long long b2_0 = brow[(tx << 1) + 0];                          \
      unsigned long long b2_1 = brow[(tx << 1) + 1];                          \
      unsigned long long b2_2 = brow[32 + (tx << 1) + 0];                     \
      unsigned long long b2_3 = brow[32 + (tx << 1) + 1];                     \
      float4 av0 = *(const float4*)&As[kk][ty << 2];                          \
      float4 av1 = *(const float4*)&As[kk][64 + (ty << 2)];                   \
      float ar[8] = {av0.x, av0.y, av0.z, av0.w, av1.x, av1.y, av1.z, av1.w}; \
      _Pragma("unroll")                                                       \
      for (int rr = 0; rr < 8; rr++) {                                        \
        unsigned long long a = dup2(ar[rr]);                                  \
        ffma2(acc[rr][0], a, b2_0); ffma2(acc[rr][1], a, b2_1);               \
        ffma2(acc[rr][2], a, b2_2); ffma2(acc[rr][3], a, b2_3);               \
      }                                                                       \
    }                                                                         \
    __syncthreads();                                                          \
  }

// ---------------------- fused QKV projection (grid.z=3) ----------------------
__global__ void __launch_bounds__(256, 2) qkv_kernel(
    const float* __restrict__ Wq, const float* __restrict__ Wk,
    const float* __restrict__ Wv,
    const float* __restrict__ bq, const float* __restrict__ bk,
    const float* __restrict__ bv) {
  int z = blockIdx.z;
  const float* A = (z == 0) ? g_qn : (z == 1) ? g_kn : g_vn;
  const float* B = (z == 0) ? Wq : (z == 1) ? Wk : Wv;
  const float* bias = (z == 0) ? bq : (z == 1) ? bk : bv;
  float* C = (z == 0) ? g_Q : (z == 1) ? g_K : g_V;
  int row0 = blockIdx.y * 128, col0 = blockIdx.x * 128;
  __shared__ float As[8][132];
  __shared__ float Bs[8][132];
  int tid = threadIdx.x;
  int lr = tid >> 1, lk = (tid & 1) << 2;
  int ty = tid >> 4, tx = tid & 15;
  unsigned long long acc[8][4];
#pragma unroll
  for (int i = 0; i < 8; i++)
#pragma unroll
    for (int j = 0; j < 4; j++) acc[i][j] = 0ull;

  GEMM_CORE(A, B, DIM, DIM, DIM)

#pragma unroll
  for (int rh = 0; rh < 2; rh++) {
#pragma unroll
    for (int ii = 0; ii < 4; ii++) {
      int i = row0 + rh * 64 + (ty << 2) + ii;
      int rr = rh * 4 + ii;
      int b = i >> 11, s = i & 2047;
#pragma unroll
      for (int ch = 0; ch < 2; ch++) {
        int j0 = col0 + ch * 64 + (tx << 2);
        float2 pA = unpack2(acc[rr][ch * 2 + 0]);
        float2 pB = unpack2(acc[rr][ch * 2 + 1]);
        float cv[4] = {pA.x + bias[j0], pA.y + bias[j0 + 1],
                       pB.x + bias[j0 + 2], pB.y + bias[j0 + 3]};
        if (z < 2) {  // HEADST: [b,h,d,s]
#pragma unroll
          for (int jj = 0; jj < 4; jj++) {
            int j = j0 + jj;
            int h = j >> 6, d = j & 63;
            C[(((size_t)(b * NHEAD + h)) * HDIM + d) * SEQ + s] = cv[jj];
          }
        } else {      // HEADS: [b,h,s,d]
          int h = j0 >> 6, d = j0 & 63;
          *(float4*)&C[(((size_t)(b * NHEAD + h)) * SEQ + s) * HDIM + d] =
              make_float4(cv[0], cv[1], cv[2], cv[3]);
        }
      }
    }
  }
}

// ------------------------------- GEMM (NT) ----------------------------------
// flags: 1=bias, 2=residual, 4=relu
__global__ void __launch_bounds__(256, 2) gemm_kernel(
    int asel, int lda,
    const float* __restrict__ Bext, int ldb,
    float* __restrict__ Cext, int csel, int ldc,
    const float* __restrict__ bias, const float* __restrict__ resid,
    int K, int flags) {
  const float* A = (const float*)devbuf(asel);
  const float* B = Bext;
  float*       C = Cext ? Cext : devbuf(csel);
  int row0 = blockIdx.y * 128, col0 = blockIdx.x * 128;
  __shared__ float As[8][132];
  __shared__ float Bs[8][132];
  int tid = threadIdx.x;
  int lr = tid >> 1, lk = (tid & 1) << 2;
  int ty = tid >> 4, tx = tid & 15;
  unsigned long long acc[8][4];
#pragma unroll
  for (int i = 0; i < 8; i++)
#pragma unroll
    for (int j = 0; j < 4; j++) acc[i][j] = 0ull;

  GEMM_CORE(A, B, lda, ldb, K)

#pragma unroll
  for (int rh = 0; rh < 2; rh++) {
#pragma unroll
    for (int ii = 0; ii < 4; ii++) {
      int i = row0 + rh * 64 + (ty << 2) + ii;
      int rr = rh * 4 + ii;
#pragma unroll
      for (int ch = 0; ch < 2; ch++) {
        int j0 = col0 + ch * 64 + (tx << 2);
        float2 pA = unpack2(acc[rr][ch * 2 + 0]);
        float2 pB = unpack2(acc[rr][ch * 2 + 1]);
        float cv[4] = {pA.x, pA.y, pB.x, pB.y};
        if (flags & 1) {
#pragma unroll
          for (int jj = 0; jj < 4; jj++) cv[jj] += bias[j0 + jj];
        }
        if (flags & 4) {
#pragma unroll
          for (int jj = 0; jj < 4; jj++) cv[jj] = fmaxf(cv[jj], 0.0f);
        }
        if (flags & 2) {
          const float* rp = resid + (size_t)i * ldc + j0;
#pragma unroll
          for (int jj = 0; jj < 4; jj++) cv[jj] += rp[jj];
        }
        *(float4*)&C[(size_t)i * ldc + j0] =
            make_float4(cv[0], cv[1], cv[2], cv[3]);
      }
    }
  }
}

// ------------------- hidden-MLP GEMM: 64x64 tiles, K=512 ---------------------
__global__ void __launch_bounds__(256) hid_kernel(
    const float* __restrict__ Ww1, const float* __restrict__ bw1) {
  int row0 = blockIdx.y * 64, col0 = blockIdx.x * 64;
  __shared__ float As[16][68];
  __shared__ float Bs[16][68];
  int tid = threadIdx.x;
  int lr = tid >> 2, lk = (tid & 3) << 2;
  int ty = tid >> 4, tx = tid & 15;
  unsigned long long acc[4][2];
#pragma unroll
  for (int i = 0; i < 4; i++) { acc[i][0] = 0ull; acc[i][1] = 0ull; }
  const float* Ap = g_qn + (size_t)(row0 + lr) * DIM + lk;
  const float* Bp = Ww1 + (size_t)(col0 + lr) * DIM + lk;
  float4 a4 = *(const float4*)Ap;
  float4 b4 = *(const float4*)Bp;
  for (int k0 = 0; k0 < DIM; k0 += 16) {
    As[lk + 0][lr] = a4.x; As[lk + 1][lr] = a4.y;
    As[lk + 2][lr] = a4.z; As[lk + 3][lr] = a4.w;
    Bs[lk + 0][lr] = b4.x; Bs[lk + 1][lr] = b4.y;
    Bs[lk + 2][lr] = b4.z; Bs[lk + 3][lr] = b4.w;
    __syncthreads();
    if (k0 + 16 < DIM) {
      Ap += 16; Bp += 16;
      a4 = *(const float4*)Ap;
      b4 = *(const float4*)Bp;
    }
#pragma unroll
    for (int kk = 0; kk < 16; kk++) {
      const unsigned long long* brow = (const unsigned long long*)&Bs[kk][0];
      unsigned long long b0 = brow[(tx << 1) + 0];
      unsigned long long b1 = brow[(tx << 1) + 1];
      float4 av = *(const float4*)&As[kk][ty << 2];
      unsigned long long a;
      a = dup2(av.x); ffma2(acc[0][0], a, b0); ffma2(acc[0][1], a, b1);
      a = dup2(av.y); ffma2(acc[1][0], a, b0); ffma2(acc[1][1], a, b1);
      a = dup2(av.z); ffma2(acc[2][0], a, b0); ffma2(acc[2][1], a, b1);
      a = dup2(av.w); ffma2(acc[3][0], a, b0); ffma2(acc[3][1], a, b1);
    }
    __syncthreads();
  }
#pragma unroll
  for (int ii = 0; ii < 4; ii++) {
    int i = row0 + (ty << 2) + ii;
    int j0 = col0 + (tx << 2);
    float2 p0 = unpack2(acc[ii][0]);
    float2 p1 = unpack2(acc[ii][1]);
    float4 o;
    o.x = fmaxf(p0.x + bw1[j0 + 0], 0.0f);
    o.y = fmaxf(p0.y + bw1[j0 + 1], 0.0f);
    o.z = fmaxf(p1.x + bw1[j0 + 2], 0.0f);
    o.w = fmaxf(p1.y + bw1[j0 + 3], 0.0f);
    *(float4*)&g_hid[(size_t)i * NHID + j0] = o;
  }
}

// -------------------- fused flash attention (mask-aware) ---------------------
// grid (SEQ/64, B*H), 256 threads. Q,K in [b,h,d,s]; V in [b,h,s,d].
// R13-proven smem online softmax.
#define NT 32           // SEQ/64 tiles
__global__ void __launch_bounds__(256, 2) flash_kernel() {
  extern __shared__ float sm[];
  float* Qs = sm;                        // [64][68] (d-major)
  float* Ks = Qs + 64 * 68;              // [2][64][68] (d-major)
  float* Vs = Ks + 2 * 64 * 68;          // [64][68] (s-major)
  float* Ps = Vs + 64 * 68;              // [64][68] row-major [q][k]
  float* alpha_s = Ps + 64 * 68;         // [64]
  float* l_s = alpha_s + 64;             // [64]
  unsigned char* Ms = (unsigned char*)(l_s + 64);   // [2][64][64]

  int z = blockIdx.y;
  int q0 = blockIdx.x * 64;
  const float* Qg = g_Q + (size_t)z * HDIM * SEQ;
  const float* Kg = g_K + (size_t)z * HDIM * SEQ;
  const float* Vg = g_V + (size_t)z * SEQ * HDIM;
  const unsigned char* Mg = g_m + (size_t)(z >> 3) * L2M;

  int tid = threadIdx.x;
  int lr = tid >> 2, lc = (tid & 3) << 4;     // loader: row 0..63, 16-col chunk
  int ty = tid >> 4, tx = tid & 15;           // compute microtile
  int r = tid >> 2, cq = tid & 3;             // softmax: row, quarter

  // Q tile (persistent): Qs[d][i] = Qg[d][q0+i]
  {
    const float* src = Qg + (size_t)lr * SEQ + q0 + lc;
    float4* dst = (float4*)&Qs[lr * 68 + lc];
#pragma unroll
    for (int u = 0; u < 4; u++) dst[u] = *(const float4*)(src + u * 4);
  }

  // prologue: prefetch K(0), M(0) into buffer 0
  {
    uint32_t kd = s2u(&Ks[lr * 68 + lc]);
    const float* ksrc = Kg + (size_t)lr * SEQ + lc;
#pragma unroll
    for (int u = 0; u < 4; u++) cpasync16(kd + u * 16, ksrc + u * 4);
    cpasync16(s2u(&Ms[lr * 64 + lc]), Mg + (size_t)(q0 + lr) * SEQ + lc);
  }
  CP_COMMIT();

  unsigned long long acc[4][2];
#pragma unroll
  for (int i = 0; i < 4; i++) { acc[i][0] = 0ull; acc[i][1] = 0ull; }
  float m_run = -INFINITY, l_run = 0.0f;

  for (int t = 0; t < NT; t++) {
    int j0 = t * 64;
    int buf = t & 1;
    float* Kb = Ks + buf * 64 * 68;
    unsigned char* Mb = Ms + buf * 64 * 64;
    __syncthreads();   // prev GEMM2 done (Vs free), Ks/Ms[buf^1] free

    // group A: V(t)
    {
      uint32_t vd = s2u(&Vs[lr * 68 + lc]);
      const float* vsrc = Vg + (size_t)(j0 + lr) * HDIM + lc;
#pragma unroll
      for (int u = 0; u < 4; u++) cpasync16(vd + u * 16, vsrc + u * 4);
    }
    CP_COMMIT();
    // group B: K(t+1), M(t+1) into the other buffer
    if (t + 1 < NT) {
      float* Kn = Ks + (buf ^ 1) * 64 * 68;
      unsigned char* Mn = Ms + (buf ^ 1) * 64 * 64;
      uint32_t kd = s2u(&Kn[lr * 68 + lc]);
      const float* ksrc = Kg + (size_t)lr * SEQ + j0 + 64 + lc;
#pragma unroll
      for (int u = 0; u < 4; u++) cpasync16(kd + u * 16, ksrc + u * 4);
      cpasync16(s2u(&Mn[lr * 64 + lc]), Mg + (size_t)(q0 + lr) * SEQ + j0 + 64 + lc);
    }
    CP_COMMIT();

    CP_WAIT(2);        // K(t), M(t) have landed
    __syncthreads();

    // ---- GEMM1: S = Q^T K (64x64x64), B pairs via LDS.64 ----
    unsigned long long s2r[4][2];
#pragma unroll
    for (int i = 0; i < 4; i++) { s2r[i][0] = 0ull; s2r[i][1] = 0ull; }
#pragma unroll 16
    for (int d = 0; d < 64; d++) {
      const unsigned long long* brow = (const unsigned long long*)&Kb[d * 68];
      unsigned long long b0 = brow[(tx << 1) + 0];
      unsigned long long b1 = brow[(tx << 1) + 1];
      float4 av = *(const float4*)&Qs[d * 68 + (ty << 2)];
      unsigned long long a;
      a = dup2(av.x); ffma2(s2r[0][0], a, b0); ffma2(s2r[0][1], a, b1);
      a = dup2(av.y); ffma2(s2r[1][0], a, b0); ffma2(s2r[1][1], a, b1);
      a = dup2(av.z); ffma2(s2r[2][0], a, b0); ffma2(s2r[2][1], a, b1);
      a = dup2(av.w); ffma2(s2r[3][0], a, b0); ffma2(s2r[3][1], a, b1);
    }
    // scale + mask, store row-major Ps[q][k]
#pragma unroll
    for (int ii = 0; ii < 4; ii++) {
      int gi = (ty << 2) + ii;
      float2 p0 = unpack2(s2r[ii][0]);
      float2 p1 = unpack2(s2r[ii][1]);
      uchar4 mm = *(const uchar4*)&Mb[gi * 64 + (tx << 2)];
      float4 sv;
      sv.x = mm.x ? -FLT_MAX : p0.x * 0.125f;
      sv.y = mm.y ? -FLT_MAX : p0.y * 0.125f;
      sv.z = mm.z ? -FLT_MAX : p1.x * 0.125f;
      sv.w = mm.w ? -FLT_MAX : p1.y * 0.125f;
      *(float4*)&Ps[gi * 68 + (tx << 2)] = sv;
    }
    __syncthreads();

    // ---- online softmax over this 64-wide tile ----
    float4 v4[4];
    float tm = -FLT_MAX;
#pragma unroll
    for (int u = 0; u < 4; u++) {
      v4[u] = *(const float4*)&Ps[r * 68 + lc + u * 4];
      tm = fmaxf(tm, fmaxf(fmaxf(v4[u].x, v4[u].y), fmaxf(v4[u].z, v4[u].w)));
    }
    tm = fmaxf(tm, __shfl_xor_sync(0xffffffffu, tm, 1));
    tm = fmaxf(tm, __shfl_xor_sync(0xffffffffu, tm, 2));
    float m_new = fmaxf(m_run, tm);
    float al = __expf(m_run - m_new);
    float psum = 0.0f;
#pragma unroll
    for (int u = 0; u < 4; u++) {
      v4[u].x = __expf(v4[u].x - m_new);
      v4[u].y = __expf(v4[u].y - m_new);
      v4[u].z = __expf(v4[u].z - m_new);
      v4[u].w = __expf(v4[u].w - m_new);
      psum += v4[u].x + v4[u].y + v4[u].z + v4[u].w;
      *(float4*)&Ps[r * 68 + lc + u * 4] = v4[u];
    }
    psum += __shfl_xor_sync(0xffffffffu, psum, 1);
    psum += __shfl_xor_sync(0xffffffffu, psum, 2);
    l_run = l_run * al + psum;
    m_run = m_new;
    if (cq == 0) alpha_s[r] = al;
    CP_WAIT(1);        // V(t) landed (group B may still be in flight)
    __syncthreads();

    // ---- GEMM2: O = O*alpha + P V (vector P reads, LDS.64 V pairs) ----
#pragma unroll
    for (int ii = 0; ii < 4; ii++) {
      unsigned long long a2 = dup2(alpha_s[(ty << 2) + ii]);
      fmul2(acc[ii][0], a2);
      fmul2(acc[ii][1], a2);
    }
#pragma unroll 4
    for (int k4 = 0; k4 < 64; k4 += 4) {
      float4 pr0 = *(const float4*)&Ps[((ty << 2) + 0) * 68 + k4];
      float4 pr1 = *(const float4*)&Ps[((ty << 2) + 1) * 68 + k4];
      float4 pr2 = *(const float4*)&Ps[((ty << 2) + 2) * 68 + k4];
      float4 pr3 = *(const float4*)&Ps[((ty << 2) + 3) * 68 + k4];
      float p0a[4] = {pr0.x, pr0.y, pr0.z, pr0.w};
      float p1a[4] = {pr1.x, pr1.y, pr1.z, pr1.w};
      float p2a[4] = {pr2.x, pr2.y, pr2.z, pr2.w};
      float p3a[4] = {pr3.x, pr3.y, pr3.z, pr3.w};
#pragma unroll
      for (int u = 0; u < 4; u++) {
        const unsigned long long* vrow =
            (const unsigned long long*)&Vs[(k4 + u) * 68];
        unsigned long long b0 = vrow[(tx << 1) + 0];
        unsigned long long b1 = vrow[(tx << 1) + 1];
        unsigned long long a;
        a = dup2(p0a[u]); ffma2(acc[0][0], a, b0); ffma2(acc[0][1], a, b1);
        a = dup2(p1a[u]); ffma2(acc[1][0], a, b0); ffma2(acc[1][1], a, b1);
        a = dup2(p2a[u]); ffma2(acc[2][0], a, b0); ffma2(acc[2][1], a, b1);
        a = dup2(p3a[u]); ffma2(acc[3][0], a, b0); ffma2(acc[3][1], a, b1);
      }
    }
  }

  if (cq == 0) l_s[r] = l_run;
  __syncthreads();
  int b = z >> 3, h = z & 7;
#pragma unroll
  for (int ii = 0; ii < 4; ii++) {
    float inv = 1.0f / l_s[(ty << 2) + ii];
    float2 p0 = unpack2(acc[ii][0]);
    float2 p1 = unpack2(acc[ii][1]);
    float4 o = make_float4(p0.x * inv, p0.y * inv, p1.x * inv, p1.y * inv);
    *(float4*)&g_O[((size_t)(b * SEQ + q0 + (ty << 2) + ii)) * DIM
                   + h * HDIM + (tx << 2)] = o;
  }
}

// ---------------------- window MLP second layer + win -----------------------
__global__ void win_kernel(const float* __restrict__ Ww2,
                           const float* __restrict__ bw2) {
  int row = blockIdx.x, tid = threadIdx.x;  // 128 threads
  __shared__ float red[128];
  red[tid] = g_hid[(size_t)row * NHID + tid] * Ww2[tid];
  __syncthreads();
  for (int o = 64; o; o >>= 1) { if (tid < o) red[tid] += red[tid + o]; __syncthreads(); }
  if (tid == 0) {
    float x = red[0] + bw2[0];
    float adj = 0.5f + 1.0f / (1.0f + expf(-x));
    int w = (int)rintf(64.0f * adj);
    w = w < 1 ? 1 : (w > 128 ? 128 : w);
    g_win[row] = w;
  }
}

// ------------------------- per-row features (dm/imp/var) --------------------
__global__ void rowfeat_kernel() {
  int row = blockIdx.x;               // b*2048 + t
  int t = row & 2047;
  int tid = threadIdx.x;              // 128
  const float* q0 = g_qn + (size_t)row * DIM;
  float sdm = 0, sab = 0, sq = 0, sq2 = 0;
  for (int d = tid; d < DIM; d += 128) {
    float q = q0[d];
    sq += q; sq2 += q * q;
    if (t + 1 < SEQ) { float a = fabsf(q0[DIM + d] - q);      sdm += 0.4f * a; sab += a; }
    if (t + 2 < SEQ) { float a = fabsf(q0[2*DIM + d] - q) * 0.5f;         sdm += 0.3f * a; }
    if (t + 3 < SEQ) { float a = fabsf(q0[3*DIM + d] - q) * (1.0f/3.0f);  sdm += 0.2f * a; }
    if (t + 5 < SEQ) { float a = fabsf(q0[5*DIM + d] - q) * 0.2f;         sdm += 0.1f * a; }
  }
  __shared__ float red[128];
  red[tid] = sdm; __syncthreads();
  for (int o = 64; o; o >>= 1) { if (tid < o) red[tid] += red[tid + o]; __syncthreads(); }
  float Sdm = red[0]; __syncthreads();
  red[tid] = sab; __syncthreads();
  for (int o = 64; o; o >>= 1) { if (tid < o) red[tid] += red[tid + o]; __syncthreads(); }
  float Sab = red[0]; __syncthreads();
  red[tid] = sq; __syncthreads();
  for (int o = 64; o; o >>= 1) { if (tid < o) red[tid] += red[tid + o]; __syncthreads(); }
  float Sq = red[0]; __syncthreads();
  red[tid] = sq2; __syncthreads();
  for (int o = 64; o; o >>= 1) { if (tid < o) red[tid] += red[tid + o]; __syncthreads(); }
  float Sq2 = red[0];
  if (tid == 0) {
    g_dm[row] = Sdm * (1.0f / DIM);
    float ch  = Sab * (1.0f / DIM);
    float mag = sqrtf(Sq2);
    g_imp[row] = 0.5f * mag + 0.5f * ch;
    g_rv[row]  = (Sq2 - Sq * Sq * (1.0f / DIM)) * (1.0f / (DIM - 1));
  }
}

// ----------------------------- per-batch stats ------------------------------
__global__ void batchstats_kernel() {
  int b = blockIdx.x, tid = threadIdx.x;  // 512 threads
  __shared__ float red[512];
  float s = 0, sv = 0, mn = FLT_MAX, mx = -FLT_MAX;
  for (int t = tid; t < SEQ; t += 512) {
    s += g_dm[b * SEQ + t];
    sv += g_rv[b * SEQ + t];
    float im = g_imp[b * SEQ + t];
    mn = fminf(mn, im); mx = fmaxf(mx, im);
  }
  red[tid] = s; __syncthreads();
  for (int o = 256; o; o >>= 1) { if (tid < o) red[tid] += red[tid + o]; __syncthreads(); }
  float mean = red[0] * (1.0f / SEQ); __syncthreads();
  float ss = 0;
  for (int t = tid; t < SEQ; t += 512) { float d = g_dm[b * SEQ + t] - mean; ss += d * d; }
  red[tid] = ss; __syncthreads();
  for (int o = 256; o; o >>= 1) { if (tid < o) red[tid] += red[tid + o]; __syncthreads(); }
  float stdv = sqrtf(red[0] * (1.0f / (SEQ - 1))); __syncthreads();
  red[tid] = sv; __syncthreads();
  for (int o = 256; o; o >>= 1) { if (tid < o) red[tid] += red[tid + o]; __syncthreads(); }
  float comp = red[0] * (1.0f / SEQ); __syncthreads();
  red[tid] = mn; __syncthreads();
  for (int o = 256; o; o >>= 1) { if (tid < o) red[tid] = fminf(red[tid], red[tid + o]); __syncthreads(); }
  float lo = red[0]; __syncthreads();
  red[tid] = mx; __syncthreads();
  for (int o = 256; o; o >>= 1) { if (tid < o) red[tid] = fmaxf(red[tid], red[tid + o]); __syncthreads(); }
  if (tid == 0) {
    g_thr[b] = mean + 0.5f * stdv;
    g_comp[b] = comp; g_lo[b] = lo; g_hi[b] = red[0];
  }
}

// ------------------- ratio + zero transient accumulators --------------------
__global__ void ratio_kernel() {
  int tid = threadIdx.x;
  if (tid < BATCH) {
    float c0 = g_comp[0], c1 = g_comp[1];
    float cmin = fminf(c0, c1), cmax = fmaxf(c0, c1);
    float nc = (g_comp[tid] - cmin) / (cmax - cmin + 1e-6f);
    float r = 0.3f * (0.5f + nc);
    g_ratio[tid] = fminf(fmaxf(r, 0.1f), 0.5f);
    g_haskp[tid] = 0; g_cnt[tid] = 0;
  }
  for (int i = tid; i < MROWS; i += 256) g_colm[i] = 0;
}

// ------------------------------- keypoints ----------------------------------
__global__ void kp_kernel() {
  int idx = blockIdx.x * 256 + threadIdx.x;
  if (idx >= MROWS) return;
  int b = idx >> 11, t = idx & 2047;
  float d = g_dm[idx], thr = g_thr[b];
  float l = (t > 0)       ? g_dm[idx - 1] : -1.0f;
  float r = (t < SEQ - 1) ? g_dm[idx + 1] : -1.0f;
  bool kp = (d > thr) && (d > l) && (d > r);
  if (t == 0 || t == SEQ - 1) kp = kp || (d > thr);
  g_kp[idx] = kp ? 1 : 0;
  if (kp) atomicOr(&g_haskp[b], 1);
}

// ----------------------- gumbel top-4 per segment ---------------------------
__global__ void gumbel_kernel(uint32_t kg0, uint32_t kg1) {
  int r = blockIdx.x;          // 0..7 = b*4 + layer
  int b = r >> 2, layer = r & 3;
  int j = threadIdx.x;         // 512
  __shared__ float red[512];
  __shared__ int   ridx[512];
  float lo = g_lo[b], hi = g_hi[b];
  float impn = (g_imp[b * SEQ + layer * 512 + j] - lo) / (hi - lo + 1e-6f);
  red[j] = impn; __syncthreads();
  for (int o = 256; o; o >>= 1) { if (j < o) red[j] += red[j + o]; __syncthreads(); }
  float rsum = red[0]; __syncthreads();
  float prob = impn / (rsum + 1e-6f);
  uint32_t x0, x1;
  tf2x32(kg0, kg1, 0u, (uint32_t)(r * 512 + j), &x0, &x1);
  uint32_t bits = x0 ^ x1;
  float u = __uint_as_float((bits >> 9) | 0x3f800000u) - 1.0f;
  const float TINY = 1.17549435e-38f;
  u = u * (1.0f - TINY) + TINY;
  u = fmaxf(TINY, u);
  float score = logf(prob + 1e-20f) - logf(-logf(u));
  float myv = score;
  for (int pick = 0; pick < 4; pick++) {
    red[j] = myv; ridx[j] = j; __syncthreads();
    for (int o = 256; o; o >>= 1) {
      if (j < o) {
        float v2 = red[j + o]; int i2 = ridx[j + o];
        if (v2 > red[j] || (v2 == red[j] && i2 < ridx[j])) { red[j] = v2; ridx[j] = i2; }
      }
      __syncthreads();
    }
    int w = ridx[0];
    if (j == w) myv = -INFINITY;
    if (j == 0) g_colm[b * SEQ + layer * 512 + w] = 1;
    __syncthreads();
  }
}

// -------------------- mask build + popcount (vectorized) ---------------------
__device__ __forceinline__ int isfb(int k) {
  return (k == 0) | (k == 511) | (k == 1023) | (k == 1535) | (k == 2047);
}
__global__ void maskbuild_kernel() {
  int row = blockIdx.x;
  int b = row >> 11, q = row & 2047;
  int w = g_win[row];
  int haskp = g_haskp[b];
  int kpq = g_kp[row];
  int fbq = isfb(q);
  unsigned char* mrow = g_m + (size_t)b * L2M + (size_t)q * SEQ;
  const unsigned char* kprow = g_kp + b * SEQ;
  const unsigned char* crow = g_colm + b * SEQ;
  int lo = q - w, hi = q + w;
  int k0 = threadIdx.x * 8;     // 256 threads x 8 bytes = 2048
  uint2 kp8 = *(const uint2*)&kprow[k0];
  uint2 c8  = *(const uint2*)&crow[k0];
  const unsigned char* kb = (const unsigned char*)&kp8;
  const unsigned char* cb = (const unsigned char*)&c8;
  unsigned char out[8];
  int cnt = 0;
#pragma unroll
  for (int u = 0; u < 8; u++) {
    int k = k0 + u;
    int v = (k >= lo) & (k <= hi);
    if (haskp) v |= kpq | kb[u];
    else       v |= fbq | isfb(k);
    v |= cb[u];
    v = v ? 1 : 0;
    out[u] = (unsigned char)v;
    cnt += v;
  }
  *(uint2*)&mrow[k0] = *(const uint2*)out;
  __shared__ int red[256];
  red[threadIdx.x] = cnt; __syncthreads();
  for (int o = 128; o; o >>= 1) { if (threadIdx.x < o) red[threadIdx.x] += red[threadIdx.x + o]; __syncthreads(); }
  if (threadIdx.x == 0) atomicAdd(&g_cnt[b], red[0]);
}

// ---------------- adaptive random fill (needed computed inline) --------------
__global__ void randfill_kernel(uint32_t q0, uint32_t q1, uint32_t k0, uint32_t k1) {
  int b = blockIdx.y;
  float dens = (float)g_cnt[b] * (1.0f / 4194304.0f);
  float nf = ceilf((g_ratio[b] - dens) * 4194304.0f);
  int needed = (int)nf;
  if (needed < 0) needed = 0;
  int j = blockIdx.x * 256 + threadIdx.x;
  if (j >= needed) return;
  uint32_t i = (uint32_t)(b * NRAND + j);
  uint32_t a, c;
  tf2x32(q0, q1, 0u, i, &a, &c);
  uint32_t qr = (a ^ c) & 2047u;
  tf2x32(k0, k1, 0u, i, &a, &c);
  uint32_t kr = (a ^ c) & 2047u;
  g_m[(size_t)b * L2M + (size_t)qr * SEQ + kr] = 1;
}

// -------------------------------- launch ------------------------------------
extern "C" void kernel_launch(void* const* d_in, const int* in_sizes, int n_in,
                              void* d_out, int out_size) {
  (void)in_sizes; (void)n_in; (void)out_size;
  const float* queries = (const float*)d_in[0];
  const float* keys    = (const float*)d_in[1];
  const float* values  = (const float*)d_in[2];
  const float* lnqg = (const float*)d_in[3];  const float* lnqb = (const float*)d_in[4];
  const float* lnkg = (const float*)d_in[5];  const float* lnkb = (const float*)d_in[6];
  const float* lnvg = (const float*)d_in[7];  const float* lnvb = (const float*)d_in[8];
  const float* Wq = (const float*)d_in[9];   const float* bq = (const float*)d_in[10];
  const float* Wk = (const float*)d_in[11];  const float* bk = (const float*)d_in[12];
  const float* Wv = (const float*)d_in[13];  const float* bv = (const float*)d_in[14];
  const float* Wo = (const float*)d_in[15];  const float* bo = (const float*)d_in[16];
  const float* Ww1 = (const float*)d_in[17]; const float* bw1 = (const float*)d_in[18];
  const float* Ww2 = (const float*)d_in[19]; const float* bw2 = (const float*)d_in[20];
  float* out = (float*)d_out;

  // lazily-created side stream + fork/join events (host objects only)
  static cudaStream_t s2 = 0;
  static cudaEvent_t evFork = 0, evJoin = 0;
  if (!s2) {
    cudaStreamCreateWithFlags(&s2, cudaStreamNonBlocking);
    cudaEventCreateWithFlags(&evFork, cudaEventDisableTiming);
    cudaEventCreateWithFlags(&evJoin, cudaEventDisableTiming);
  }

  // JAX PRNG derived keys (host-side, deterministic)
  uint32_t kg0, kg1, kq0, kq1, kk0, kk1, kql0, kql1, kkl0, kkl1;
  tf2x32(0u, 42u, 0u, 0u, &kg0, &kg1);     // fold_in(key(42), 0) -> gumbel
  tf2x32(0u, 42u, 0u, 1u, &kq0, &kq1);     // fold_in(key(42), 1) -> qr base
  tf2x32(0u, 42u, 0u, 2u, &kk0, &kk1);     // fold_in(key(42), 2) -> kr base
  tf2x32(kq0, kq1, 0u, 1u, &kql0, &kql1);  // split child 1 (lower bits)
  tf2x32(kk0, kk1, 0u, 1u, &kkl0, &kkl1);

  // dynamic smem for the flash kernel: Q + 2K + V + P (floats) + alpha,l + 2M
  const int FLASH_SMEM = (5 * 64 * 68 + 2 * 64) * 4 + 2 * 64 * 64;
  cudaFuncSetAttribute(flash_kernel, cudaFuncAttributeMaxDynamicSharedMemorySize,
                       FLASH_SMEM);

  // fused LayerNorms (q/k/v in one launch)
  dim3 gln(MROWS, 3, 1);
  ln3_kernel<<<gln, 256>>>(queries, keys, values,
                           lnqg, lnqb, lnkg, lnkb, lnvg, lnvb);

  // fork: mask pipeline on s2, QKV on main
  cudaEventRecord(evFork, 0);
  cudaStreamWaitEvent(s2, evFork, 0);

  // --- s2: window MLP + mask statistics pipeline (depends only on g_qn) ---
  dim3 ghid(2, 64, 1);     // 64x64 tiles over [4096, 128]
  hid_kernel<<<ghid, 256, 0, s2>>>(Ww1, bw1);
  win_kernel<<<MROWS, 128, 0, s2>>>(Ww2, bw2);
  rowfeat_kernel<<<MROWS, 128, 0, s2>>>();
  batchstats_kernel<<<BATCH, 512, 0, s2>>>();
  ratio_kernel<<<1, 256, 0, s2>>>();
  kp_kernel<<<MROWS / 256, 256, 0, s2>>>();
  gumbel_kernel<<<BATCH * 4, 512, 0, s2>>>(kg0, kg1);
  maskbuild_kernel<<<MROWS, 256, 0, s2>>>();
  randfill_kernel<<<dim3(NRAND / 256, BATCH, 1), 256, 0, s2>>>(kql0, kql1, kkl0, kkl1);
  cudaEventRecord(evJoin, s2);

  // --- main: fused QKV projections ---
  dim3 gqkv(4, 32, 3);
  qkv_kernel<<<gqkv, 256>>>(Wq, Wk, Wv, bq, bk, bv);

  // join, then fused attention
  cudaStreamWaitEvent(0, evJoin, 0);
  dim3 gf(SEQ / 64, BATCH * NHEAD, 1);
  flash_kernel<<<gf, 256, FLASH_SMEM>>>();

  // output projection + bias + residual
  dim3 gbig(4, 32, 1);
  gemm_kernel<<<gbig, 256>>>(7, DIM, Wo, DIM, out, -1, DIM, bo, queries, DIM, 1 | 2);
}